// round 4
// baseline (speedup 1.0000x reference)
#include <cuda_runtime.h>
#include <cstdint>

#define BB 32
#define CC 256
#define PP 32
#define HWD 3136
#define KT 32
#define CT 128
#define TPB 98          // k-tiles per (b,ct) segment: 3136/32
#define NSEG 64         // BB * 2 c-halves
#define NTILES 6272     // NSEG * TPB
#define NCTA 444        // 3 * 148 SMs: perfectly balanced round-robin wave
#define PS 36           // padded smem k-stride: conflict-free, 16B-multiple
#define NTHREADS 128

__device__ float g_att[BB * HWD];                 // 0.4 MB sigmoid gate
__device__ float g_part[NCTA * 2 * PP * CT];      // 14.5 MB flush slots
// slot layout: g_part[(cta*2 + slot)*4096 + p*CT + c_local]

#define FMA2(d, a, b) asm("fma.rn.f32x2 %0, %1, %2, %0;" : "+l"(d) : "l"(a), "l"(b))

__device__ __forceinline__ void cpasync16(uint32_t s, const void* g) {
    asm volatile("cp.async.cg.shared.global [%0], [%1], 16;\n" :: "r"(s), "l"(g));
}
__device__ __forceinline__ void cpcommit() {
    asm volatile("cp.async.commit_group;\n" ::: "memory");
}
template <int N>
__device__ __forceinline__ void cpwait() {
    asm volatile("cp.async.wait_group %0;\n" :: "n"(N) : "memory");
}

// ---------------- att = sigmoid(w . pa + bias) ----------------
__global__ __launch_bounds__(256)
void rfe_att_kernel(const float* __restrict__ pa,
                    const float* __restrict__ conv_w,
                    const float* __restrict__ conv_b)
{
    __shared__ float w_s[PP];
    if (threadIdx.x < PP) w_s[threadIdx.x] = conv_w[threadIdx.x];
    __syncthreads();
    const int idx = blockIdx.x * 256 + threadIdx.x;    // 0..B*HWD-1 exact
    const int b  = idx / HWD;
    const int hw = idx - b * HWD;
    const float* pp = pa + (size_t)b * PP * HWD + hw;
    float z = conv_b[0];
    #pragma unroll
    for (int p = 0; p < PP; ++p) z += pp[(size_t)p * HWD] * w_s[p];
    g_att[idx] = 1.f / (1.f + __expf(-z));
}

// ---------------- flat-scheduled main GEMM ----------------
__global__ __launch_bounds__(NTHREADS, 3)
void rfe_main_kernel(const float* __restrict__ x,
                     const float* __restrict__ pa)
{
    __shared__ __align__(16) float pa_s[2][PP][PS];
    __shared__ __align__(16) float x_s[2][CT][PS];

    const int tid = threadIdx.x;
    const int n   = blockIdx.x;
    const int u0  = (n * NTILES) / NCTA;
    const int u1  = ((n + 1) * NTILES) / NCTA;

    // gmem load mapping: 8 float4 per KT-float row
    const int kq  = tid & 7;
    const int row = tid >> 3;   // 0..15
    // compute mapping: per-warp 8p x (32 lanes x 4 c)
    const int p_idx = tid >> 5;
    const int c_idx = tid & 31;

    // current / next tile coords
    int seg  = u0 / TPB;
    int kt   = u0 - seg * TPB;
    int b    = seg >> 1, ct = seg & 1;

    unsigned long long acc[8][4];
    #pragma unroll
    for (int i = 0; i < 8; ++i)
        #pragma unroll
        for (int j = 0; j < 4; ++j) acc[i][j] = 0ull;

    // ---- prologue: tile u0 ----
    float4 pa_r[2], att_r;
    {
        const float* pb = pa + (size_t)b * PP * HWD + kt * KT + kq * 4;
        const float* xb = x  + ((size_t)(b * CC + ct * CT)) * HWD + kt * KT + kq * 4;
        const float* ab = g_att + (size_t)b * HWD + kt * KT + kq * 4;
        #pragma unroll
        for (int r = 0; r < 2; ++r)
            pa_r[r] = *(const float4*)(pb + (size_t)(row + 16 * r) * HWD);
        att_r = *(const float4*)ab;
        #pragma unroll
        for (int r = 0; r < 8; ++r)
            cpasync16(__cvta_generic_to_shared(&x_s[0][row + 16 * r][kq * 4]),
                      xb + (size_t)(row + 16 * r) * HWD);
        cpcommit();
    }

    int slot = 0;
    for (int u = u0; u < u1; ++u) {
        const int cbuf = (u - u0) & 1;
        const bool last = (u + 1 == u1);

        // next tile coords
        int kt_n = kt + 1, seg_n = seg;
        if (kt_n == TPB) { kt_n = 0; seg_n = seg + 1; }
        const int b_n = seg_n >> 1, ct_n = seg_n & 1;

        if (!last) {
            const float* xb = x + ((size_t)(b_n * CC + ct_n * CT)) * HWD + kt_n * KT + kq * 4;
            #pragma unroll
            for (int r = 0; r < 8; ++r)
                cpasync16(__cvta_generic_to_shared(&x_s[cbuf ^ 1][row + 16 * r][kq * 4]),
                          xb + (size_t)(row + 16 * r) * HWD);
            cpcommit();
        }

        // store gated pa tile (regs -> smem), folding att
        #pragma unroll
        for (int r = 0; r < 2; ++r) {
            float4 v = pa_r[r];
            v.x *= att_r.x; v.y *= att_r.y; v.z *= att_r.z; v.w *= att_r.w;
            *(float4*)&pa_s[cbuf][row + 16 * r][kq * 4] = v;
        }

        // prefetch pa/att regs for next tile (overlaps GEMM)
        if (!last) {
            const float* pb = pa + (size_t)b_n * PP * HWD + kt_n * KT + kq * 4;
            const float* ab = g_att + (size_t)b_n * HWD + kt_n * KT + kq * 4;
            #pragma unroll
            for (int r = 0; r < 2; ++r)
                pa_r[r] = *(const float4*)(pb + (size_t)(row + 16 * r) * HWD);
            att_r = *(const float4*)ab;
        }

        if (!last) cpwait<1>(); else cpwait<0>();
        __syncthreads();

        // GEMM on buffer cbuf: packed f32x2 over k-pairs
        #pragma unroll
        for (int k = 0; k < KT; k += 4) {
            ulonglong2 xv[4];
            #pragma unroll
            for (int j = 0; j < 4; ++j)
                xv[j] = *(const ulonglong2*)&x_s[cbuf][c_idx + 32 * j][k];
            #pragma unroll
            for (int i = 0; i < 8; ++i) {
                const ulonglong2 av = *(const ulonglong2*)&pa_s[cbuf][p_idx + 4 * i][k];
                #pragma unroll
                for (int j = 0; j < 4; ++j) FMA2(acc[i][j], av.x, xv[j].x);
                #pragma unroll
                for (int j = 0; j < 4; ++j) FMA2(acc[i][j], av.y, xv[j].y);
            }
        }
        __syncthreads();

        // flush at segment boundary / end of range
        if (last || seg_n != seg) {
            float* outp = g_part + ((size_t)(n * 2 + slot)) * (PP * CT);
            #pragma unroll
            for (int i = 0; i < 8; ++i) {
                const int p = p_idx + 4 * i;
                #pragma unroll
                for (int j = 0; j < 4; ++j) {
                    const int cl = c_idx + 32 * j;
                    const unsigned long long v = acc[i][j];
                    outp[p * CT + cl] =
                        __uint_as_float((unsigned)(v & 0xffffffffull)) +
                        __uint_as_float((unsigned)(v >> 32));
                    acc[i][j] = 0ull;
                }
            }
            ++slot;
        }

        seg = seg_n; kt = kt_n; b = b_n; ct = ct_n;
    }
}

// ---------------- segment reduce ----------------
__device__ __forceinline__ int cta_of(int t) {
    int n = (int)(((long long)t * NCTA) / NTILES);
    while ((long long)(n + 1) * NTILES / NCTA <= t) ++n;
    while ((long long)n * NTILES / NCTA > t) --n;
    return n;
}

__global__ __launch_bounds__(256)
void rfe_reduce_kernel(float4* __restrict__ out)
{
    const int idx4 = blockIdx.x * 256 + threadIdx.x;   // 0..65535
    const int e = idx4 * 4;
    const int bb  = e >> 13;            // / 8192
    const int rem = e & 8191;
    const int p   = rem >> 8;           // / 256
    const int c   = rem & 255;
    const int ct  = c >> 7;
    const int cl  = c & 127;
    const int seg = bb * 2 + ct;
    const int pe  = p * CT + cl;        // multiple of 4

    const int t0 = seg * TPB;
    const int n0 = cta_of(t0);
    const int n1 = cta_of(t0 + TPB - 1);

    float4 s = make_float4(0.f, 0.f, 0.f, 0.f);
    for (int n = n0; n <= n1; ++n) {
        const int first_seg = (int)((long long)n * NTILES / NCTA) / TPB;
        const int slot = (seg == first_seg) ? 0 : 1;
        const float4 v = *(const float4*)(g_part + ((size_t)(n * 2 + slot)) * (PP * CT) + pe);
        s.x += v.x; s.y += v.y; s.z += v.z; s.w += v.w;
    }
    out[idx4] = s;
}

extern "C" void kernel_launch(void* const* d_in, const int* in_sizes, int n_in,
                              void* d_out, int out_size)
{
    const float* x      = (const float*)d_in[0];  // [32,256,56,56]
    const float* pa     = (const float*)d_in[1];  // [32,32,56,56]
    const float* conv_w = (const float*)d_in[2];  // [32]
    const float* conv_b = (const float*)d_in[3];  // [1]
    float* out = (float*)d_out;                   // [32, 8192]

    rfe_att_kernel<<<(BB * HWD) / 256, 256>>>(pa, conv_w, conv_b);
    rfe_main_kernel<<<NCTA, NTHREADS>>>(x, pa);
    rfe_reduce_kernel<<<(BB * PP * CC) / 1024, 256>>>((float4*)out);
}

// round 8
// speedup vs baseline: 1.3624x; 1.3624x over previous
#include <cuda_runtime.h>
#include <cstdint>

#define BB 32
#define CC 256
#define PP 32
#define HWD 3136
#define NCH 7
#define CHUNK 448       // HWD / NCH
#define KT 32           // k-tile: 32 fp32 = 128 B row (SW128 atom)
#define NKT 14          // CHUNK / KT
#define CT 128          // c tile per CTA
#define NCT 2           // CC / CT
#define NTHREADS 128

__device__ float g_att[BB * HWD];                    // sigmoid gate
__device__ float g_part[NCH * BB * CC * PP];         // 7.3 MB partials, [ch][b][c][p]

__device__ __forceinline__ uint32_t smem_u32(const void* p) {
    uint32_t a;
    asm("{ .reg .u64 t; cvta.to.shared.u64 t, %1; cvt.u32.u64 %0, t; }" : "=r"(a) : "l"(p));
    return a;
}
__device__ __forceinline__ uint32_t swz(uint32_t o) { return o ^ ((o >> 3) & 0x70); }
__device__ __forceinline__ uint32_t f2tf32(float f) {
    uint32_t r;
    asm("cvt.rna.tf32.f32 %0, %1;" : "=r"(r) : "f"(f));
    return r;
}
__device__ __forceinline__ uint32_t u2tf32(uint32_t u) { return f2tf32(__uint_as_float(u)); }

__device__ __forceinline__ void cpasync16(uint32_t s, const void* g) {
    asm volatile("cp.async.cg.shared.global [%0], [%1], 16;\n" :: "r"(s), "l"(g));
}
__device__ __forceinline__ void cpcommit() {
    asm volatile("cp.async.commit_group;\n" ::: "memory");
}
template <int N>
__device__ __forceinline__ void cpwait() {
    asm volatile("cp.async.wait_group %0;\n" :: "n"(N) : "memory");
}

#define LDSM_X4(r0, r1, r2, r3, addr)                                        \
    asm volatile("ldmatrix.sync.aligned.m8n8.x4.shared.b16 {%0,%1,%2,%3}, [%4];" \
        : "=r"(r0), "=r"(r1), "=r"(r2), "=r"(r3) : "r"(addr))

#define MMA_TF32(d, a0, a1, a2, a3, b0, b1)                                  \
    asm volatile("mma.sync.aligned.m16n8k8.row.col.f32.tf32.tf32.f32 "       \
        "{%0,%1,%2,%3}, {%4,%5,%6,%7}, {%8,%9}, {%0,%1,%2,%3};"              \
        : "+f"((d)[0]), "+f"((d)[1]), "+f"((d)[2]), "+f"((d)[3])             \
        : "r"(a0), "r"(a1), "r"(a2), "r"(a3), "r"(b0), "r"(b1))

// ---------------- att = sigmoid(w . pa + bias), float4 ----------------
__global__ __launch_bounds__(256)
void rfe_att_kernel(const float* __restrict__ pa,
                    const float* __restrict__ conv_w,
                    const float* __restrict__ conv_b)
{
    __shared__ float w_s[PP];
    if (threadIdx.x < PP) w_s[threadIdx.x] = conv_w[threadIdx.x];
    __syncthreads();
    const int idx = blockIdx.x * 256 + threadIdx.x;   // 0..25087 exact
    const int b  = idx / (HWD / 4);
    const int hw = (idx - b * (HWD / 4)) * 4;
    const float* pp = pa + (size_t)b * PP * HWD + hw;
    const float bias = conv_b[0];
    float4 z = make_float4(bias, bias, bias, bias);
    #pragma unroll
    for (int p = 0; p < PP; ++p) {
        const float4 v = *(const float4*)(pp + (size_t)p * HWD);
        const float w = w_s[p];
        z.x += v.x * w; z.y += v.y * w; z.z += v.z * w; z.w += v.w * w;
    }
    float4 a;
    a.x = 1.f / (1.f + __expf(-z.x));
    a.y = 1.f / (1.f + __expf(-z.y));
    a.z = 1.f / (1.f + __expf(-z.z));
    a.w = 1.f / (1.f + __expf(-z.w));
    *(float4*)(g_att + (size_t)b * HWD + hw) = a;
}

// ---------------- main GEMM via mma.sync tf32 ----------------
struct SmemT {
    float xa[2][CT * KT];   // x tiles, SW128-swizzled 128B rows   (2 x 16 KB)
    float pb[2][PP * KT];   // gated pa tiles, swizzled            (2 x 4 KB)
};

__global__ __launch_bounds__(NTHREADS, 3)
void rfe_main_kernel(const float* __restrict__ x,
                     const float* __restrict__ pa)
{
    __shared__ SmemT sm;

    const int tid   = threadIdx.x;
    const int chunk = blockIdx.x;   // 0..6
    const int ct    = blockIdx.y;   // 0..1
    const int b     = blockIdx.z;   // 0..31
    const int hw0   = chunk * CHUNK;

    // gmem->smem mapping: 8 lanes x 16B per 128B row
    const int kq  = tid & 7;
    const int row = tid >> 3;   // 0..15
    const float* xg = x  + ((size_t)(b * CC + ct * CT)) * HWD + hw0 + kq * 4;
    const float* pg = pa + ((size_t)b * PP) * HWD + hw0 + kq * 4;
    const float* ag = g_att + (size_t)b * HWD + hw0 + kq * 4;

    // MMA lane mapping
    const int w    = tid >> 5;       // warp: c rows [w*32, w*32+32)
    const int lane = tid & 31;
    const int q    = lane >> 3, lr = lane & 7;
    const int g8   = lane >> 2, tg = lane & 3;
    // A ldsm base: rows (w*32 + (q&1)*8 + lr), byte col (q>>1)*16
    const uint32_t a_off0 = (uint32_t)((w * 32 + (q & 1) * 8 + lr) * 128 + (q >> 1) * 16);
    // B ldsm base: rows lr, byte col q*16
    const uint32_t b_off0 = (uint32_t)(lr * 128 + q * 16);
    const uint32_t xab[2] = { smem_u32(&sm.xa[0][0]), smem_u32(&sm.xa[1][0]) };
    const uint32_t pbb[2] = { smem_u32(&sm.pb[0][0]), smem_u32(&sm.pb[1][0]) };

    float d_[2][4][4];
    #pragma unroll
    for (int mi = 0; mi < 2; ++mi)
        #pragma unroll
        for (int ni = 0; ni < 4; ++ni)
            #pragma unroll
            for (int r = 0; r < 4; ++r) d_[mi][ni][r] = 0.f;

    // ---- prologue: pa/att regs tile 0, cp.async x tile 0 ----
    float4 pa_r[2], att_r;
    #pragma unroll
    for (int r = 0; r < 2; ++r)
        pa_r[r] = *(const float4*)(pg + (size_t)(row + 16 * r) * HWD);
    att_r = *(const float4*)(ag);
    #pragma unroll
    for (int r = 0; r < 8; ++r)
        cpasync16(xab[0] + swz((uint32_t)(row + 16 * r) * 128 + kq * 16),
                  xg + (size_t)(row + 16 * r) * HWD);
    cpcommit();

    for (int t = 0; t < NKT; ++t) {
        const int cbuf = t & 1;
        const bool last = (t + 1 == NKT);

        if (!last) {
            const int kn = (t + 1) * KT;
            #pragma unroll
            for (int r = 0; r < 8; ++r)
                cpasync16(xab[cbuf ^ 1] + swz((uint32_t)(row + 16 * r) * 128 + kq * 16),
                          xg + (size_t)(row + 16 * r) * HWD + kn);
            cpcommit();
        }

        // store gated pa tile (regs -> swizzled smem)
        #pragma unroll
        for (int r = 0; r < 2; ++r) {
            float4 v = pa_r[r];
            v.x *= att_r.x; v.y *= att_r.y; v.z *= att_r.z; v.w *= att_r.w;
            const uint32_t addr = pbb[cbuf] + swz((uint32_t)(row + 16 * r) * 128 + kq * 16);
            asm volatile("st.shared.v4.b32 [%0], {%1, %2, %3, %4};"
                :: "r"(addr), "r"(__float_as_uint(v.x)), "r"(__float_as_uint(v.y)),
                   "r"(__float_as_uint(v.z)), "r"(__float_as_uint(v.w)) : "memory");
        }

        // prefetch pa/att regs for t+1 (overlaps MMA phase)
        if (!last) {
            const int kn = (t + 1) * KT;
            #pragma unroll
            for (int r = 0; r < 2; ++r)
                pa_r[r] = *(const float4*)(pg + (size_t)(row + 16 * r) * HWD + kn);
            att_r = *(const float4*)(ag + kn);
        }

        if (!last) cpwait<1>(); else cpwait<0>();
        __syncthreads();

        // ---- B fragments for whole k-tile: [ni][kk][2], tf32 ----
        uint32_t bf_[4][4][2];
        #pragma unroll
        for (int ni = 0; ni < 4; ++ni) {
            #pragma unroll
            for (int j = 0; j < 2; ++j) {
                uint32_t r0, r1, r2, r3;
                LDSM_X4(r0, r1, r2, r3,
                        pbb[cbuf] + swz(b_off0 + (uint32_t)ni * 1024 + (uint32_t)j * 64));
                bf_[ni][2 * j][0]     = u2tf32(r0);
                bf_[ni][2 * j][1]     = u2tf32(r1);
                bf_[ni][2 * j + 1][0] = u2tf32(r2);
                bf_[ni][2 * j + 1][1] = u2tf32(r3);
            }
        }
        // ---- A fragments + MMA ----
        #pragma unroll
        for (int mi = 0; mi < 2; ++mi) {
            #pragma unroll
            for (int kk = 0; kk < 4; ++kk) {
                uint32_t a0, a1, a2, a3;
                LDSM_X4(a0, a1, a2, a3,
                        xab[cbuf] + swz(a_off0 + (uint32_t)mi * 2048 + (uint32_t)kk * 32));
                a0 = u2tf32(a0); a1 = u2tf32(a1); a2 = u2tf32(a2); a3 = u2tf32(a3);
                #pragma unroll
                for (int ni = 0; ni < 4; ++ni)
                    MMA_TF32(d_[mi][ni], a0, a1, a2, a3,
                             bf_[ni][kk][0], bf_[ni][kk][1]);
            }
        }
        __syncthreads();
    }

    // ---- epilogue: partials [ch][b][c][p], full 32B sectors ----
    float* part = g_part + ((size_t)(chunk * BB + b) * CC + ct * CT + w * 32) * PP;
    #pragma unroll
    for (int mi = 0; mi < 2; ++mi) {
        #pragma unroll
        for (int ni = 0; ni < 4; ++ni) {
            float* r0p = part + (size_t)(mi * 16 + g8) * PP + ni * 8 + 2 * tg;
            *(float2*)r0p            = make_float2(d_[mi][ni][0], d_[mi][ni][1]);
            *(float2*)(r0p + 8 * PP) = make_float2(d_[mi][ni][2], d_[mi][ni][3]);
        }
    }
}

// ---------------- reduce over chunks + [c][p] -> [p][c] transpose ----------------
__global__ __launch_bounds__(256)
void rfe_reduce_kernel(float* __restrict__ out)
{
    __shared__ float buf[CC * 33];
    const int b = blockIdx.x;
    for (int i4 = threadIdx.x; i4 < CC * PP / 4; i4 += 256) {
        float4 s = make_float4(0.f, 0.f, 0.f, 0.f);
        #pragma unroll
        for (int ch = 0; ch < NCH; ++ch) {
            const float4 v = *(const float4*)(g_part +
                ((size_t)(ch * BB + b)) * (CC * PP) + (size_t)i4 * 4);
            s.x += v.x; s.y += v.y; s.z += v.z; s.w += v.w;
        }
        const int idx = i4 * 4;
        const int c = idx >> 5, p = idx & 31;
        float* bp = &buf[c * 33 + p];
        bp[0] = s.x; bp[1] = s.y; bp[2] = s.z; bp[3] = s.w;
    }
    __syncthreads();
    float* ob = out + (size_t)b * (PP * CC);
    for (int o = threadIdx.x; o < PP * CC; o += 256) {
        const int p = o >> 8, c = o & 255;
        ob[o] = buf[c * 33 + p];
    }
}

extern "C" void kernel_launch(void* const* d_in, const int* in_sizes, int n_in,
                              void* d_out, int out_size)
{
    const float* x      = (const float*)d_in[0];  // [32,256,56,56]
    const float* pa     = (const float*)d_in[1];  // [32,32,56,56]
    const float* conv_w = (const float*)d_in[2];  // [32]
    const float* conv_b = (const float*)d_in[3];  // [1]
    float* out = (float*)d_out;                   // [32, 8192]

    rfe_att_kernel<<<(BB * HWD / 4) / 256, 256>>>(pa, conv_w, conv_b);
    dim3 grid(NCH, NCT, BB);
    rfe_main_kernel<<<grid, NTHREADS>>>(x, pa);
    rfe_reduce_kernel<<<BB, 256>>>(out);
}

// round 10
// speedup vs baseline: 1.4366x; 1.0545x over previous
#include <cuda_runtime.h>
#include <cstdint>

#define BB 32
#define CC 256
#define PP 32
#define HWD 3136
#define NCH 7
#define CHUNK 448       // HWD / NCH
#define KT 32           // k-tile: 32 fp32 = 128 B row (SW128 atom)
#define NKT 14          // CHUNK / KT
#define CT 128          // c tile per CTA
#define NCT 2           // CC / CT
#define NTHREADS 128

__device__ float g_part[NCH * BB * CC * PP];         // 7.3 MB partials, [ch][b][c][p]

__device__ __forceinline__ uint32_t smem_u32(const void* p) {
    uint32_t a;
    asm("{ .reg .u64 t; cvta.to.shared.u64 t, %1; cvt.u32.u64 %0, t; }" : "=r"(a) : "l"(p));
    return a;
}
__device__ __forceinline__ uint32_t swz(uint32_t o) { return o ^ ((o >> 3) & 0x70); }
__device__ __forceinline__ uint32_t f2tf32(float f) {
    uint32_t r;
    asm("cvt.rna.tf32.f32 %0, %1;" : "=r"(r) : "f"(f));
    return r;
}
__device__ __forceinline__ uint32_t u2tf32(uint32_t u) { return f2tf32(__uint_as_float(u)); }

__device__ __forceinline__ void cpasync16(uint32_t s, const void* g) {
    asm volatile("cp.async.cg.shared.global [%0], [%1], 16;\n" :: "r"(s), "l"(g));
}
__device__ __forceinline__ void cpcommit() {
    asm volatile("cp.async.commit_group;\n" ::: "memory");
}
template <int N>
__device__ __forceinline__ void cpwait() {
    asm volatile("cp.async.wait_group %0;\n" :: "n"(N) : "memory");
}

#define LDSM_X4(r0, r1, r2, r3, addr)                                        \
    asm volatile("ldmatrix.sync.aligned.m8n8.x4.shared.b16 {%0,%1,%2,%3}, [%4];" \
        : "=r"(r0), "=r"(r1), "=r"(r2), "=r"(r3) : "r"(addr))

#define MMA_TF32(d, a0, a1, a2, a3, b0, b1)                                  \
    asm volatile("mma.sync.aligned.m16n8k8.row.col.f32.tf32.tf32.f32 "       \
        "{%0,%1,%2,%3}, {%4,%5,%6,%7}, {%8,%9}, {%0,%1,%2,%3};"              \
        : "+f"((d)[0]), "+f"((d)[1]), "+f"((d)[2]), "+f"((d)[3])             \
        : "r"(a0), "r"(a1), "r"(a2), "r"(a3), "r"(b0), "r"(b1))

// ---------------- fused main GEMM (att computed in-tile) ----------------
struct SmemT {
    float xa[2][CT * KT];       // x tiles, SW128-swizzled 128B rows (2 x 16 KB)
    float pb[2][PP * KT];       // gated pa tiles, swizzled          (2 x 4 KB)
    float att_part[2][4][KT];   // [parity][warp][k] partial dot     (1 KB)
    float w_s[PP];
};

__global__ __launch_bounds__(NTHREADS, 3)
void rfe_main_kernel(const float* __restrict__ x,
                     const float* __restrict__ pa,
                     const float* __restrict__ conv_w,
                     const float* __restrict__ conv_b)
{
    __shared__ SmemT sm;

    const int tid   = threadIdx.x;
    const int chunk = blockIdx.x;   // 0..6
    const int ct    = blockIdx.y;   // 0..1
    const int b     = blockIdx.z;   // 0..31
    const int hw0   = chunk * CHUNK;

    // gmem->smem mapping: 8 lanes x 16B per 128B row
    const int kq  = tid & 7;
    const int row = tid >> 3;   // 0..15
    const float* xg = x  + ((size_t)(b * CC + ct * CT)) * HWD + hw0 + kq * 4;
    const float* pg = pa + ((size_t)b * PP) * HWD + hw0 + kq * 4;

    // MMA lane mapping
    const int w    = tid >> 5;       // warp: c rows [w*32, w*32+32)
    const int lane = tid & 31;
    const int q    = lane >> 3, lr = lane & 7;
    const int g8   = lane >> 2, tg = lane & 3;
    const uint32_t a_off0 = (uint32_t)((w * 32 + (q & 1) * 8 + lr) * 128 + (q >> 1) * 16);
    const uint32_t b_off0 = (uint32_t)(lr * 128 + q * 16);
    const uint32_t xab[2] = { smem_u32(&sm.xa[0][0]), smem_u32(&sm.xa[1][0]) };
    const uint32_t pbb[2] = { smem_u32(&sm.pb[0][0]), smem_u32(&sm.pb[1][0]) };

    float d_[2][4][4];
    #pragma unroll
    for (int mi = 0; mi < 2; ++mi)
        #pragma unroll
        for (int ni = 0; ni < 4; ++ni)
            #pragma unroll
            for (int r = 0; r < 4; ++r) d_[mi][ni][r] = 0.f;

    // ---- prologue ----
    if (tid < PP) sm.w_s[tid] = conv_w[tid];
    const float bias = conv_b[0];

    float4 pa_r[2];
    #pragma unroll
    for (int r = 0; r < 2; ++r)
        pa_r[r] = *(const float4*)(pg + (size_t)(row + 16 * r) * HWD);
    #pragma unroll
    for (int r = 0; r < 8; ++r)
        cpasync16(xab[0] + swz((uint32_t)(row + 16 * r) * 128 + kq * 16),
                  xg + (size_t)(row + 16 * r) * HWD);
    cpcommit();

    __syncthreads();                   // w_s visible
    const float w0 = sm.w_s[row], w1 = sm.w_s[row + 16];

    // att partials for tile 0
    {
        float4 s;
        s.x = w0 * pa_r[0].x + w1 * pa_r[1].x;
        s.y = w0 * pa_r[0].y + w1 * pa_r[1].y;
        s.z = w0 * pa_r[0].z + w1 * pa_r[1].z;
        s.w = w0 * pa_r[0].w + w1 * pa_r[1].w;
        #pragma unroll
        for (int d8 = 8; d8 <= 16; d8 <<= 1) {
            s.x += __shfl_xor_sync(0xffffffffu, s.x, d8);
            s.y += __shfl_xor_sync(0xffffffffu, s.y, d8);
            s.z += __shfl_xor_sync(0xffffffffu, s.z, d8);
            s.w += __shfl_xor_sync(0xffffffffu, s.w, d8);
        }
        if (lane < 8) *(float4*)&sm.att_part[0][w][lane * 4] = s;
    }
    __syncthreads();                   // att_part[0] visible

    for (int t = 0; t < NKT; ++t) {
        const int cbuf = t & 1;
        const bool last = (t + 1 == NKT);

        // (a) att for tile t -> gate pa_r -> STS pb[cbuf]
        {
            float4 z = make_float4(bias, bias, bias, bias);
            #pragma unroll
            for (int w2 = 0; w2 < 4; ++w2) {
                const float4 v = *(const float4*)&sm.att_part[cbuf][w2][kq * 4];
                z.x += v.x; z.y += v.y; z.z += v.z; z.w += v.w;
            }
            float4 a4;
            a4.x = 1.f / (1.f + __expf(-z.x));
            a4.y = 1.f / (1.f + __expf(-z.y));
            a4.z = 1.f / (1.f + __expf(-z.z));
            a4.w = 1.f / (1.f + __expf(-z.w));
            #pragma unroll
            for (int r = 0; r < 2; ++r) {
                float4 v = pa_r[r];
                v.x *= a4.x; v.y *= a4.y; v.z *= a4.z; v.w *= a4.w;
                const uint32_t addr = pbb[cbuf] + swz((uint32_t)(row + 16 * r) * 128 + kq * 16);
                asm volatile("st.shared.v4.b32 [%0], {%1, %2, %3, %4};"
                    :: "r"(addr), "r"(__float_as_uint(v.x)), "r"(__float_as_uint(v.y)),
                       "r"(__float_as_uint(v.z)), "r"(__float_as_uint(v.w)) : "memory");
            }
        }

        // (c) prefetch x tile t+1
        if (!last) {
            const int kn = (t + 1) * KT;
            #pragma unroll
            for (int r = 0; r < 8; ++r)
                cpasync16(xab[cbuf ^ 1] + swz((uint32_t)(row + 16 * r) * 128 + kq * 16),
                          xg + (size_t)(row + 16 * r) * HWD + kn);
            cpcommit();
        }
        // (d) prefetch pa regs t+1
        float4 pa_n[2];
        if (!last) {
            const int kn = (t + 1) * KT;
            #pragma unroll
            for (int r = 0; r < 2; ++r)
                pa_n[r] = *(const float4*)(pg + (size_t)(row + 16 * r) * HWD + kn);
        }

        if (!last) cpwait<1>(); else cpwait<0>();
        __syncthreads();   // sync1: pb[cbuf] + x tile t ready

        // ---- B fragments: [ni][kk][2], tf32 ----
        uint32_t bf_[4][4][2];
        #pragma unroll
        for (int ni = 0; ni < 4; ++ni) {
            #pragma unroll
            for (int j = 0; j < 2; ++j) {
                uint32_t r0, r1, r2, r3;
                LDSM_X4(r0, r1, r2, r3,
                        pbb[cbuf] + swz(b_off0 + (uint32_t)ni * 1024 + (uint32_t)j * 64));
                bf_[ni][2 * j][0]     = u2tf32(r0);
                bf_[ni][2 * j][1]     = u2tf32(r1);
                bf_[ni][2 * j + 1][0] = u2tf32(r2);
                bf_[ni][2 * j + 1][1] = u2tf32(r3);
            }
        }
        // ---- A fragments + MMA ----
        #pragma unroll
        for (int mi = 0; mi < 2; ++mi) {
            #pragma unroll
            for (int kk = 0; kk < 4; ++kk) {
                uint32_t a0, a1, a2, a3;
                LDSM_X4(a0, a1, a2, a3,
                        xab[cbuf] + swz(a_off0 + (uint32_t)mi * 2048 + (uint32_t)kk * 32));
                a0 = u2tf32(a0); a1 = u2tf32(a1); a2 = u2tf32(a2); a3 = u2tf32(a3);
                #pragma unroll
                for (int ni = 0; ni < 4; ++ni)
                    MMA_TF32(d_[mi][ni], a0, a1, a2, a3,
                             bf_[ni][kk][0], bf_[ni][kk][1]);
            }
        }

        // (e) att partials for tile t+1 (pa_n landed during MMA phase)
        if (!last) {
            float4 s;
            s.x = w0 * pa_n[0].x + w1 * pa_n[1].x;
            s.y = w0 * pa_n[0].y + w1 * pa_n[1].y;
            s.z = w0 * pa_n[0].z + w1 * pa_n[1].z;
            s.w = w0 * pa_n[0].w + w1 * pa_n[1].w;
            #pragma unroll
            for (int d8 = 8; d8 <= 16; d8 <<= 1) {
                s.x += __shfl_xor_sync(0xffffffffu, s.x, d8);
                s.y += __shfl_xor_sync(0xffffffffu, s.y, d8);
                s.z += __shfl_xor_sync(0xffffffffu, s.z, d8);
                s.w += __shfl_xor_sync(0xffffffffu, s.w, d8);
            }
            if (lane < 8) *(float4*)&sm.att_part[cbuf ^ 1][w][lane * 4] = s;
            pa_r[0] = pa_n[0]; pa_r[1] = pa_n[1];
            __syncthreads();   // sync2: smem free for next iteration
        }
    }

    // ---- epilogue: partials [ch][b][c][p], full 32B sectors ----
    float* part = g_part + ((size_t)(chunk * BB + b) * CC + ct * CT + w * 32) * PP;
    #pragma unroll
    for (int mi = 0; mi < 2; ++mi) {
        #pragma unroll
        for (int ni = 0; ni < 4; ++ni) {
            float* r0p = part + (size_t)(mi * 16 + g8) * PP + ni * 8 + 2 * tg;
            *(float2*)r0p            = make_float2(d_[mi][ni][0], d_[mi][ni][1]);
            *(float2*)(r0p + 8 * PP) = make_float2(d_[mi][ni][2], d_[mi][ni][3]);
        }
    }
}

// ---------------- reduce over chunks + [c][p] -> [p][c] transpose ----------------
__global__ __launch_bounds__(256)
void rfe_reduce_kernel(float* __restrict__ out)
{
    __shared__ float buf[128 * 33];
    const int b    = blockIdx.x >> 1;
    const int half = blockIdx.x & 1;           // c range [half*128, half*128+128)
    for (int i4 = threadIdx.x; i4 < 128 * PP / 4; i4 += 256) {
        const int idx = i4 * 4;
        const int cl = idx >> 5, p = idx & 31;
        const size_t goff = ((size_t)b * CC + half * 128 + cl) * PP + p;
        float4 s = make_float4(0.f, 0.f, 0.f, 0.f);
        #pragma unroll
        for (int ch = 0; ch < NCH; ++ch) {
            const float4 v = *(const float4*)(g_part + (size_t)ch * (BB * CC * PP) + goff);
            s.x += v.x; s.y += v.y; s.z += v.z; s.w += v.w;
        }
        float* bp = &buf[cl * 33 + p];
        bp[0] = s.x; bp[1] = s.y; bp[2] = s.z; bp[3] = s.w;
    }
    __syncthreads();
    float* ob = out + (size_t)b * (PP * CC) + half * 128;
    for (int o = threadIdx.x; o < PP * 128; o += 256) {
        const int p = o >> 7, cl = o & 127;
        ob[p * CC + cl] = buf[cl * 33 + p];
    }
}

extern "C" void kernel_launch(void* const* d_in, const int* in_sizes, int n_in,
                              void* d_out, int out_size)
{
    const float* x      = (const float*)d_in[0];  // [32,256,56,56]
    const float* pa     = (const float*)d_in[1];  // [32,32,56,56]
    const float* conv_w = (const float*)d_in[2];  // [32]
    const float* conv_b = (const float*)d_in[3];  // [1]
    float* out = (float*)d_out;                   // [32, 8192]

    dim3 grid(NCH, NCT, BB);
    rfe_main_kernel<<<grid, NTHREADS>>>(x, pa, conv_w, conv_b);
    rfe_reduce_kernel<<<BB * 2, 256>>>(out);
}

// round 12
// speedup vs baseline: 1.5180x; 1.0567x over previous
#include <cuda_runtime.h>
#include <cstdint>

#define BB 32
#define CC 256
#define PP 32
#define HWD 3136
#define NCH 7
#define CHUNK 448       // HWD / NCH
#define KT 32           // k-tile: 32 fp32 = 128 B row (SW128 atom)
#define NKT 14          // CHUNK / KT
#define CT 128          // c tile per CTA
#define NCT 2           // CC / CT
#define NTHREADS 128

__device__ float g_part[NCH * BB * PP * CC];         // 7.3 MB partials, [ch][b][p][c]

__device__ __forceinline__ uint32_t smem_u32(const void* p) {
    uint32_t a;
    asm("{ .reg .u64 t; cvta.to.shared.u64 t, %1; cvt.u32.u64 %0, t; }" : "=r"(a) : "l"(p));
    return a;
}
__device__ __forceinline__ uint32_t swz(uint32_t o) { return o ^ ((o >> 3) & 0x70); }
__device__ __forceinline__ uint32_t f2tf32(float f) {
    uint32_t r;
    asm("cvt.rna.tf32.f32 %0, %1;" : "=r"(r) : "f"(f));
    return r;
}
__device__ __forceinline__ uint32_t u2tf32(uint32_t u) { return f2tf32(__uint_as_float(u)); }

__device__ __forceinline__ void cpasync16(uint32_t s, const void* g) {
    asm volatile("cp.async.cg.shared.global [%0], [%1], 16;\n" :: "r"(s), "l"(g));
}
__device__ __forceinline__ void cpcommit() {
    asm volatile("cp.async.commit_group;\n" ::: "memory");
}
template <int N>
__device__ __forceinline__ void cpwait() {
    asm volatile("cp.async.wait_group %0;\n" :: "n"(N) : "memory");
}

#define LDSM_X4(r0, r1, r2, r3, addr)                                        \
    asm volatile("ldmatrix.sync.aligned.m8n8.x4.shared.b16 {%0,%1,%2,%3}, [%4];" \
        : "=r"(r0), "=r"(r1), "=r"(r2), "=r"(r3) : "r"(addr))

#define MMA_TF32(d, a0, a1, a2, a3, b0, b1)                                  \
    asm volatile("mma.sync.aligned.m16n8k8.row.col.f32.tf32.tf32.f32 "       \
        "{%0,%1,%2,%3}, {%4,%5,%6,%7}, {%8,%9}, {%0,%1,%2,%3};"              \
        : "+f"((d)[0]), "+f"((d)[1]), "+f"((d)[2]), "+f"((d)[3])             \
        : "r"(a0), "r"(a1), "r"(a2), "r"(a3), "r"(b0), "r"(b1))

// ---------------- fused main GEMM (att computed in-tile) ----------------
struct SmemT {
    float xa[2][CT * KT];       // x tiles, SW128-swizzled 128B rows (2 x 16 KB)
    float pb[2][PP * KT];       // gated pa tiles, swizzled          (2 x 4 KB)
    float att_part[2][4][KT];   // [parity][warp][k] partial dot     (1 KB)
    float w_s[PP];
};
#define TPAD 132   // transpose buffer row pad (conflict-free both phases)

__global__ __launch_bounds__(NTHREADS, 4)
void rfe_main_kernel(const float* __restrict__ x,
                     const float* __restrict__ pa,
                     const float* __restrict__ conv_w,
                     const float* __restrict__ conv_b)
{
    __shared__ SmemT sm;

    const int tid   = threadIdx.x;
    const int chunk = blockIdx.x;   // 0..6
    const int ct    = blockIdx.y;   // 0..1
    const int b     = blockIdx.z;   // 0..31
    const int hw0   = chunk * CHUNK;

    // gmem->smem mapping: 8 lanes x 16B per 128B row
    const int kq  = tid & 7;
    const int row = tid >> 3;   // 0..15
    const float* xg = x  + ((size_t)(b * CC + ct * CT)) * HWD + hw0 + kq * 4;
    const float* pg = pa + ((size_t)b * PP) * HWD + hw0 + kq * 4;

    // MMA lane mapping
    const int w    = tid >> 5;       // warp: c rows [w*32, w*32+32)
    const int lane = tid & 31;
    const int q    = lane >> 3, lr = lane & 7;
    const int g8   = lane >> 2, tg = lane & 3;
    const uint32_t a_off0 = (uint32_t)((w * 32 + (q & 1) * 8 + lr) * 128 + (q >> 1) * 16);
    const uint32_t b_off0 = (uint32_t)(lr * 128 + q * 16);
    const uint32_t xab[2] = { smem_u32(&sm.xa[0][0]), smem_u32(&sm.xa[1][0]) };
    const uint32_t pbb[2] = { smem_u32(&sm.pb[0][0]), smem_u32(&sm.pb[1][0]) };

    float d_[2][4][4];
    #pragma unroll
    for (int mi = 0; mi < 2; ++mi)
        #pragma unroll
        for (int ni = 0; ni < 4; ++ni)
            #pragma unroll
            for (int r = 0; r < 4; ++r) d_[mi][ni][r] = 0.f;

    // ---- prologue ----
    if (tid < PP) sm.w_s[tid] = conv_w[tid];
    const float bias = conv_b[0];

    float4 pa_r[2];
    #pragma unroll
    for (int r = 0; r < 2; ++r)
        pa_r[r] = *(const float4*)(pg + (size_t)(row + 16 * r) * HWD);
    #pragma unroll
    for (int r = 0; r < 8; ++r)
        cpasync16(xab[0] + swz((uint32_t)(row + 16 * r) * 128 + kq * 16),
                  xg + (size_t)(row + 16 * r) * HWD);
    cpcommit();

    __syncthreads();                   // w_s visible
    const float w0 = sm.w_s[row], w1 = sm.w_s[row + 16];

    // att partials for tile 0
    {
        float4 s;
        s.x = w0 * pa_r[0].x + w1 * pa_r[1].x;
        s.y = w0 * pa_r[0].y + w1 * pa_r[1].y;
        s.z = w0 * pa_r[0].z + w1 * pa_r[1].z;
        s.w = w0 * pa_r[0].w + w1 * pa_r[1].w;
        #pragma unroll
        for (int d8 = 8; d8 <= 16; d8 <<= 1) {
            s.x += __shfl_xor_sync(0xffffffffu, s.x, d8);
            s.y += __shfl_xor_sync(0xffffffffu, s.y, d8);
            s.z += __shfl_xor_sync(0xffffffffu, s.z, d8);
            s.w += __shfl_xor_sync(0xffffffffu, s.w, d8);
        }
        if (lane < 8) *(float4*)&sm.att_part[0][w][lane * 4] = s;
    }
    __syncthreads();                   // att_part[0] visible

    for (int t = 0; t < NKT; ++t) {
        const int cbuf = t & 1;
        const bool last = (t + 1 == NKT);

        // (a) att for tile t -> gate pa_r -> STS pb[cbuf]
        {
            float4 z = make_float4(bias, bias, bias, bias);
            #pragma unroll
            for (int w2 = 0; w2 < 4; ++w2) {
                const float4 v = *(const float4*)&sm.att_part[cbuf][w2][kq * 4];
                z.x += v.x; z.y += v.y; z.z += v.z; z.w += v.w;
            }
            float4 a4;
            a4.x = 1.f / (1.f + __expf(-z.x));
            a4.y = 1.f / (1.f + __expf(-z.y));
            a4.z = 1.f / (1.f + __expf(-z.z));
            a4.w = 1.f / (1.f + __expf(-z.w));
            #pragma unroll
            for (int r = 0; r < 2; ++r) {
                float4 v = pa_r[r];
                v.x *= a4.x; v.y *= a4.y; v.z *= a4.z; v.w *= a4.w;
                const uint32_t addr = pbb[cbuf] + swz((uint32_t)(row + 16 * r) * 128 + kq * 16);
                asm volatile("st.shared.v4.b32 [%0], {%1, %2, %3, %4};"
                    :: "r"(addr), "r"(__float_as_uint(v.x)), "r"(__float_as_uint(v.y)),
                       "r"(__float_as_uint(v.z)), "r"(__float_as_uint(v.w)) : "memory");
            }
        }

        // (c) prefetch x tile t+1
        if (!last) {
            const int kn = (t + 1) * KT;
            #pragma unroll
            for (int r = 0; r < 8; ++r)
                cpasync16(xab[cbuf ^ 1] + swz((uint32_t)(row + 16 * r) * 128 + kq * 16),
                          xg + (size_t)(row + 16 * r) * HWD + kn);
            cpcommit();
        }
        // (d) prefetch pa regs t+1
        float4 pa_n[2];
        if (!last) {
            const int kn = (t + 1) * KT;
            #pragma unroll
            for (int r = 0; r < 2; ++r)
                pa_n[r] = *(const float4*)(pg + (size_t)(row + 16 * r) * HWD + kn);
        }

        if (!last) cpwait<1>(); else cpwait<0>();
        __syncthreads();   // sync1: pb[cbuf] + x tile t ready

        // ---- B fragments: [ni][kk][2], tf32 ----
        uint32_t bf_[4][4][2];
        #pragma unroll
        for (int ni = 0; ni < 4; ++ni) {
            #pragma unroll
            for (int j = 0; j < 2; ++j) {
                uint32_t r0, r1, r2, r3;
                LDSM_X4(r0, r1, r2, r3,
                        pbb[cbuf] + swz(b_off0 + (uint32_t)ni * 1024 + (uint32_t)j * 64));
                bf_[ni][2 * j][0]     = u2tf32(r0);
                bf_[ni][2 * j][1]     = u2tf32(r1);
                bf_[ni][2 * j + 1][0] = u2tf32(r2);
                bf_[ni][2 * j + 1][1] = u2tf32(r3);
            }
        }
        // ---- A fragments + MMA ----
        #pragma unroll
        for (int mi = 0; mi < 2; ++mi) {
            #pragma unroll
            for (int kk = 0; kk < 4; ++kk) {
                uint32_t a0, a1, a2, a3;
                LDSM_X4(a0, a1, a2, a3,
                        xab[cbuf] + swz(a_off0 + (uint32_t)mi * 2048 + (uint32_t)kk * 32));
                a0 = u2tf32(a0); a1 = u2tf32(a1); a2 = u2tf32(a2); a3 = u2tf32(a3);
                #pragma unroll
                for (int ni = 0; ni < 4; ++ni)
                    MMA_TF32(d_[mi][ni], a0, a1, a2, a3,
                             bf_[ni][kk][0], bf_[ni][kk][1]);
            }
        }

        // (e) att partials for tile t+1 (pa_n landed during MMA phase)
        if (!last) {
            float4 s;
            s.x = w0 * pa_n[0].x + w1 * pa_n[1].x;
            s.y = w0 * pa_n[0].y + w1 * pa_n[1].y;
            s.z = w0 * pa_n[0].z + w1 * pa_n[1].z;
            s.w = w0 * pa_n[0].w + w1 * pa_n[1].w;
            #pragma unroll
            for (int d8 = 8; d8 <= 16; d8 <<= 1) {
                s.x += __shfl_xor_sync(0xffffffffu, s.x, d8);
                s.y += __shfl_xor_sync(0xffffffffu, s.y, d8);
                s.z += __shfl_xor_sync(0xffffffffu, s.z, d8);
                s.w += __shfl_xor_sync(0xffffffffu, s.w, d8);
            }
            if (lane < 8) *(float4*)&sm.att_part[cbuf ^ 1][w][lane * 4] = s;
            pa_r[0] = pa_n[0]; pa_r[1] = pa_n[1];
            __syncthreads();   // sync2: smem free for next iteration
        }
    }

    // ---- epilogue: transpose in smem, write [ch][b][p][c] coalesced ----
    __syncthreads();                       // all LDSM reads of tiles done
    float* buf = (float*)&sm;              // 32 x TPAD floats (reuses xa) = 16.9 KB
    // store: addr = p*TPAD + c  (conflict-free: bank = (8*tg + g8) mod 32, all distinct)
    #pragma unroll
    for (int mi = 0; mi < 2; ++mi) {
        #pragma unroll
        for (int ni = 0; ni < 4; ++ni) {
            const int p = ni * 8 + 2 * tg;
            const int c = w * 32 + mi * 16 + g8;
            buf[p * TPAD + c]           = d_[mi][ni][0];
            buf[(p + 1) * TPAD + c]     = d_[mi][ni][1];
            buf[p * TPAD + c + 8]       = d_[mi][ni][2];
            buf[(p + 1) * TPAD + c + 8] = d_[mi][ni][3];
        }
    }
    __syncthreads();
    float* part = g_part + ((size_t)(chunk * BB + b) * PP) * CC + ct * CT;
    #pragma unroll
    for (int i = tid; i < PP * CT / 4; i += NTHREADS) {   // 8 iterations
        const int p  = i >> 5;
        const int c4 = (i & 31) * 4;
        const float4 v = make_float4(buf[p * TPAD + c4],     buf[p * TPAD + c4 + 1],
                                     buf[p * TPAD + c4 + 2], buf[p * TPAD + c4 + 3]);
        *(float4*)(part + (size_t)p * CC + c4) = v;
    }
}

// ---------------- reduce over chunks: pure coalesced strided sum ----------------
__global__ __launch_bounds__(256)
void rfe_reduce_kernel(float4* __restrict__ out)
{
    const int idx4 = blockIdx.x * 256 + threadIdx.x;   // 0..65535
    const float4* gp = (const float4*)g_part;
    float4 s = gp[idx4];
    #pragma unroll
    for (int ch = 1; ch < NCH; ++ch) {
        const float4 v = gp[(size_t)ch * (BB * PP * CC / 4) + idx4];
        s.x += v.x; s.y += v.y; s.z += v.z; s.w += v.w;
    }
    out[idx4] = s;
}

extern "C" void kernel_launch(void* const* d_in, const int* in_sizes, int n_in,
                              void* d_out, int out_size)
{
    const float* x      = (const float*)d_in[0];  // [32,256,56,56]
    const float* pa     = (const float*)d_in[1];  // [32,32,56,56]
    const float* conv_w = (const float*)d_in[2];  // [32]
    const float* conv_b = (const float*)d_in[3];  // [1]
    float* out = (float*)d_out;                   // [32, 8192]

    dim3 grid(NCH, NCT, BB);
    rfe_main_kernel<<<grid, NTHREADS>>>(x, pa, conv_w, conv_b);
    rfe_reduce_kernel<<<(BB * PP * CC / 4) / 256, 256>>>((float4*)out);
}